// round 9
// baseline (speedup 1.0000x reference)
#include <cuda_runtime.h>
#include <cuda_fp16.h>
#include <math.h>
#include <stdint.h>

// ---------------- problem constants ----------------
#define TOK   16384
#define DIM   1024
#define DFF   4096
#define NEXP  8
#define CAP   3277
#define TM    128
#define PADMAX (TOK + NEXP*TM)          // 17408
#define MAXROWTILES (PADMAX/TM)         // 136
#define KC    64                         // K chunk (fp16 elems)
#define STAGE 32768                      // A 16K + B 16K
#define NSTAGE 3
#define SMEM_REQ (NSTAGE*STAGE + 1024)   // 99328; x2 CTAs = 198656 <= 227KB
#define NB_CVT1 1024                     // w1-convert blocks in prep
#define NB_ROUT 8192                     // router blocks (2 tokens each)
#define CVT2_YEXT 32                     // extra grid-y rows on pass-1 gemm

// ---------------- device scratch ----------------
__device__ unsigned char g_selmask[TOK];
__device__ unsigned char g_kept[NEXP * TOK];
__device__ signed char   g_final[TOK];
__device__ int g_cnt[NEXP];
__device__ int g_fill[NEXP];
__device__ int g_off[NEXP + 1];
__device__ int g_perm[PADMAX];
__device__ __half g_Ag[(size_t)PADMAX * DIM];        // gathered x, fp16
__device__ __half g_H [(size_t)PADMAX * DFF];        // gelu intermediate, fp16
__device__ __half g_W1[(size_t)NEXP * DFF * DIM];    // W1^T fp16
__device__ __half g_W2[(size_t)NEXP * DIM * DFF];    // W2^T fp16

// ---------------- helpers ----------------
__device__ __forceinline__ uint32_t smem_u32(const void* p) {
    return (uint32_t)__cvta_generic_to_shared(p);
}
#define SWZ128(o) ((o) ^ (((o) >> 3) & 0x70))

#define CP16(dst, src) \
    asm volatile("cp.async.cg.shared.global [%0], [%1], 16;" :: "r"(dst), "l"(src) : "memory")
#define CP_COMMIT() asm volatile("cp.async.commit_group;" ::: "memory")
#define CP_WAIT1()  asm volatile("cp.async.wait_group 1;" ::: "memory")

__device__ __forceinline__ void ldsm4(uint32_t& r0, uint32_t& r1, uint32_t& r2,
                                      uint32_t& r3, uint32_t addr) {
    asm volatile("ldmatrix.sync.aligned.m8n8.x4.shared.b16 {%0,%1,%2,%3}, [%4];"
                 : "=r"(r0), "=r"(r1), "=r"(r2), "=r"(r3) : "r"(addr));
}

__device__ __forceinline__ void mma16816(float* c, const uint32_t* a,
                                         uint32_t b0, uint32_t b1) {
    asm volatile(
        "mma.sync.aligned.m16n8k16.row.col.f32.f16.f16.f32 "
        "{%0,%1,%2,%3}, {%4,%5,%6,%7}, {%8,%9}, {%0,%1,%2,%3};"
        : "+f"(c[0]), "+f"(c[1]), "+f"(c[2]), "+f"(c[3])
        : "r"(a[0]), "r"(a[1]), "r"(a[2]), "r"(a[3]), "r"(b0), "r"(b1));
}

__device__ __forceinline__ float gelu_exact(float v) {
    return 0.5f * v * (1.0f + erff(v * 0.70710678118654752f));
}

// transpose+convert one 32x32 tile: src fp32 [R rows, C cols] (+e offset)
// -> dst fp16 [C rows, R cols]; tsh = 32x33 float scratch
__device__ __forceinline__ void cvt_tile(const float* __restrict__ s,
                                         __half* __restrict__ d,
                                         float* tsh, int R, int C,
                                         int r0, int c0, int tx, int ty)
{
#pragma unroll
    for (int i = 0; i < 4; i++)
        tsh[(ty + i * 8) * 33 + tx] = s[(size_t)(r0 + ty + i * 8) * C + c0 + tx];
    __syncthreads();
#pragma unroll
    for (int i = 0; i < 4; i++) {
        int orow = c0 + ty + i * 8;
        int ocol = r0 + tx;
        d[(size_t)orow * R + ocol] = __float2half(tsh[tx * 33 + ty + i * 8]);
    }
    __syncthreads();
}

// ---------------- routing / prep kernels ----------------
__global__ void init_kernel() {
    int i = threadIdx.x;
    if (i < NEXP) { g_cnt[i] = 0; g_fill[i] = 0; }
}

// fat prep: blocks [0, NB_CVT1) convert W1 (fp32 [E,DIM,DFF] -> fp16 [E,DFF,DIM]);
// blocks [NB_CVT1, NB_CVT1+NB_ROUT) run the router for 2 tokens each.
__global__ __launch_bounds__(256) void prep_kernel(
    const float* __restrict__ x, const float* __restrict__ noise,
    const float* __restrict__ rw, const float* __restrict__ rb,
    const float* __restrict__ w1, __half* __restrict__ w1dst)
{
    __shared__ float sh[2 * NEXP * 128];   // 8KB: router red[2][8][128] / cvt 32x33
    int bid = blockIdx.x;
    int tid = threadIdx.x;

    if (bid < NB_CVT1) {
        // 32 tiles per block; 32768 tiles total over [E][32 rowtiles][128 coltiles]
        int tx = tid & 31, ty = tid >> 5;
#pragma unroll 1
        for (int it = 0; it < 32; it++) {
            int g = bid * 32 + it;
            int e = g >> 12;               // / 4096 tiles per expert
            int rem = g & 4095;
            int tr = rem & 31;             // row tile (DIM/32)
            int tc = rem >> 5;             // col tile (DFF/32)
            cvt_tile(w1 + (size_t)e * DIM * DFF,
                     w1dst + (size_t)e * DFF * DIM,
                     sh, DIM, DFF, tr * 32, tc * 32, tx, ty);
        }
        return;
    }

    // router: 2 tokens per block
    int t = (bid - NB_CVT1) * 2 + (tid >> 7);
    int lt = tid & 127;
    float* red = sh + (tid >> 7) * (NEXP * 128);
    const float4* xr4 = reinterpret_cast<const float4*>(x + (size_t)t * DIM);
    const float4* rw4 = reinterpret_cast<const float4*>(rw);
    float acc[NEXP];
#pragma unroll
    for (int e = 0; e < NEXP; e++) acc[e] = 0.f;
#pragma unroll
    for (int it = 0; it < 2; it++) {
        int idx = lt + it * 128;           // DIM/4 = 256
        float4 xv = xr4[idx];
#pragma unroll
        for (int e = 0; e < NEXP; e++) {
            float4 wv = rw4[e * 256 + idx];
            acc[e] += xv.x * wv.x + xv.y * wv.y + xv.z * wv.z + xv.w * wv.w;
        }
    }
#pragma unroll
    for (int e = 0; e < NEXP; e++) red[e * 128 + lt] = acc[e];
    __syncthreads();
    for (int s = 64; s > 0; s >>= 1) {
        if (lt < s) {
#pragma unroll
            for (int e = 0; e < NEXP; e++)
                red[e * 128 + lt] += red[e * 128 + lt + s];
        }
        __syncthreads();
    }
    if (lt == 0) {
        float lg[NEXP];
#pragma unroll
        for (int e = 0; e < NEXP; e++)
            lg[e] = red[e * 128] + rb[e] + noise[t * NEXP + e] * 0.02f;
        int e1 = 0;
#pragma unroll
        for (int e = 1; e < NEXP; e++) if (lg[e] > lg[e1]) e1 = e;
        int e2 = -1;
#pragma unroll
        for (int e = 0; e < NEXP; e++) {
            if (e == e1) continue;
            if (e2 < 0 || lg[e] > lg[e2]) e2 = e;
        }
        g_selmask[t] = (unsigned char)((1 << e1) | (1 << e2));
    }
}

// per-expert capacity filter via ballot words + block scan (8 blocks x 512 thr)
__global__ __launch_bounds__(512) void rank_kernel()
{
    int e = blockIdx.x;
    int tid = threadIdx.x;                 // 0..511, each owns 32 tokens
    union { uint4 v[2]; unsigned char b[32]; } u;
    u.v[0] = reinterpret_cast<const uint4*>(g_selmask)[tid * 2];
    u.v[1] = reinterpret_cast<const uint4*>(g_selmask)[tid * 2 + 1];
    uint32_t mask = 0;
#pragma unroll
    for (int j = 0; j < 32; j++)
        mask |= (uint32_t)((u.b[j] >> e) & 1) << j;
    int cnt = __popc(mask);
    __shared__ int sc[512];
    sc[tid] = cnt;
    __syncthreads();
    for (int s = 1; s < 512; s <<= 1) {
        int add = (tid >= s) ? sc[tid - s] : 0;
        __syncthreads();
        sc[tid] += add;
        __syncthreads();
    }
    int base = sc[tid] - cnt;              // exclusive prefix
    union { uint4 v[2]; unsigned char b[32]; } o;
#pragma unroll
    for (int j = 0; j < 32; j++) {
        int m = (mask >> j) & 1;
        int rank = base + __popc(mask & ((1u << j) - 1u));
        o.b[j] = (unsigned char)(m && rank < CAP);
    }
    reinterpret_cast<uint4*>(g_kept + (size_t)e * TOK)[tid * 2]     = o.v[0];
    reinterpret_cast<uint4*>(g_kept + (size_t)e * TOK)[tid * 2 + 1] = o.v[1];
}

__global__ __launch_bounds__(256) void finalize_kernel()
{
    __shared__ int loc[NEXP];
    if (threadIdx.x < NEXP) loc[threadIdx.x] = 0;
    __syncthreads();
    int t = blockIdx.x * 256 + threadIdx.x;
    unsigned char mask = g_selmask[t];
    int f = -1;
#pragma unroll
    for (int e = NEXP - 1; e >= 0; e--) {
        if (((mask >> e) & 1) && g_kept[e * TOK + t]) { f = e; break; }
    }
    g_final[t] = (signed char)f;
    if (f >= 0) atomicAdd(&loc[f], 1);
    __syncthreads();
    if (threadIdx.x < NEXP && loc[threadIdx.x] > 0)
        atomicAdd(&g_cnt[threadIdx.x], loc[threadIdx.x]);
}

__global__ void offsets_kernel()
{
    if (threadIdx.x == 0 && blockIdx.x == 0) {
        int o = 0;
        g_off[0] = 0;
        for (int e = 0; e < NEXP; e++) {
            o += ((g_cnt[e] + TM - 1) / TM) * TM;
            g_off[e + 1] = o;
        }
    }
}

__global__ __launch_bounds__(256) void perminit_kernel()
{
    int i = blockIdx.x * 256 + threadIdx.x;
    if (i < PADMAX) g_perm[i] = TOK;
}

__global__ __launch_bounds__(256) void place_kernel()
{
    int t = blockIdx.x * 256 + threadIdx.x;
    if (t >= TOK) return;
    int f = g_final[t];
    if (f >= 0) {
        int pos = g_off[f] + atomicAdd(&g_fill[f], 1);
        g_perm[pos] = t;
    }
}

// fat gather: blocks [0,PADMAX) gather x rows by g_perm (fp16);
// blocks [PADMAX, PADMAX+64) zero dropped-token output rows.
__global__ __launch_bounds__(256) void gather_kernel(
    const float* __restrict__ x, float* __restrict__ out)
{
    int bid = blockIdx.x;
    int tid = threadIdx.x;
    if (bid < PADMAX) {
        int tok = g_perm[bid];
        float4 v = make_float4(0.f, 0.f, 0.f, 0.f);
        if (tok < TOK)
            v = reinterpret_cast<const float4*>(x + (size_t)tok * DIM)[tid];
        __half h[4];
        h[0] = __float2half(v.x); h[1] = __float2half(v.y);
        h[2] = __float2half(v.z); h[3] = __float2half(v.w);
        reinterpret_cast<uint2*>(g_Ag + (size_t)bid * DIM)[tid] =
            *reinterpret_cast<uint2*>(h);
        return;
    }
    __shared__ int list[256];
    __shared__ int cnt;
    if (tid == 0) cnt = 0;
    __syncthreads();
    int t = (bid - PADMAX) * 256 + tid;
    if (g_final[t] < 0) { int p = atomicAdd(&cnt, 1); list[p] = t; }
    __syncthreads();
    float4 z = make_float4(0.f, 0.f, 0.f, 0.f);
    for (int i = 0; i < cnt; i++) {
        size_t row = (size_t)list[i] * DIM;
        reinterpret_cast<float4*>(out + row)[tid] = z;  // 256*4 = 1024
    }
}

// ---------------- HMMA GEMM (both FFN passes) ----------------
// D[128x128] = A[128 x K] * B^T, B: [N_TOT x K] row-major (k contiguous).
// single fp16 term, fp32 accum. 3-stage cp.async pipeline, 2 CTAs/SM.
// mode 1: +b1 -> gelu -> fp16 -> g_H; also carries W2-convert blocks
//         (blockIdx.y >= MAXROWTILES) overlapping DRAM work with HMMA waves.
// mode 2: +b2 -> scatter fp32 rows to out[token]
__global__ __launch_bounds__(256, 2) void gemm_kernel(
    const __half* __restrict__ A, const __half* __restrict__ B,
    const float* __restrict__ bias, float* __restrict__ out,
    int K_TOT, int N_TOT, int mode,
    const float* __restrict__ w2src, __half* __restrict__ w2dst)
{
    extern __shared__ __align__(1024) char smem_raw[];
    int tid = threadIdx.x;

    if (blockIdx.y >= MAXROWTILES) {
        // W2 convert: fp32 [E,DFF,DIM] -> fp16 [E,DIM,DFF]; 32 tiles per block
        float* tsh = reinterpret_cast<float*>(smem_raw);
        int cb = (blockIdx.y - MAXROWTILES) * gridDim.x + blockIdx.x; // 0..1023
        int tx = tid & 31, ty = tid >> 5;
#pragma unroll 1
        for (int it = 0; it < 32; it++) {
            int g = cb * 32 + it;
            int e = g >> 12;               // 4096 tiles per expert
            int rem = g & 4095;
            int tr = rem & 127;            // row tile (DFF/32)
            int tc = rem >> 7;             // col tile (DIM/32)
            cvt_tile(w2src + (size_t)e * DFF * DIM,
                     w2dst + (size_t)e * DIM * DFF,
                     tsh, DFF, DIM, tr * 32, tc * 32, tx, ty);
        }
        return;
    }

    int row0 = blockIdx.y * TM;
    if (row0 >= g_off[NEXP]) return;
    int e = 0;
#pragma unroll
    for (int i = 0; i < NEXP; i++) if (row0 >= g_off[i + 1]) e = i + 1;
    int n0 = blockIdx.x * 128;

    uint32_t sb = (smem_u32(smem_raw) + 1023) & ~1023u;

    int lane = tid & 31;
    int wid = tid >> 5;
    int wm = wid & 3;          // warp m position (4 x 32 rows)
    int wn = wid >> 2;         // warp n position (2 x 64 cols)
    int lrow = (lane & 7) + ((lane >> 3) & 1) * 8;
    int lkh  = (lane >> 4) * 8;

    const size_t eN = (size_t)e * N_TOT;
    const int C = K_TOT >> 6;

    // stage fill: 2048 x 16B cp.async (A + B, 128x64 fp16 each)
    auto fill_stage = [&](int s, int c) {
        uint32_t st = sb + s * STAGE;
        int k0 = c * KC;
#pragma unroll
        for (int j = 0; j < 4; j++) {
            int u = tid + j * 256;
            int row = u >> 3, kp = u & 7;
            uint32_t so = SWZ128(row * 128 + kp * 16);
            size_t gi = (size_t)(row0 + row) * K_TOT + k0 + kp * 8;
            CP16(st + so, (const char*)(A + gi));
            size_t gb = (eN + n0 + row) * K_TOT + k0 + kp * 8;
            CP16(st + 16384 + so, (const char*)(B + gb));
        }
    };

    float acc[2][8][4];
#pragma unroll
    for (int mt = 0; mt < 2; mt++)
#pragma unroll
        for (int nf = 0; nf < 8; nf++)
#pragma unroll
            for (int q = 0; q < 4; q++) acc[mt][nf][q] = 0.f;

    fill_stage(0, 0); CP_COMMIT();
    fill_stage(1, 1); CP_COMMIT();

    for (int c = 0; c < C; ++c) {
        int s = c % 3;
        CP_WAIT1();
        __syncthreads();
        // refill stage (c+2)%3 == (c-1)%3, consumed at iter c-1 (safe: end sync)
        if (c + 2 < C) fill_stage((c + 2) % 3, c + 2);
        CP_COMMIT();
        uint32_t st = sb + s * STAGE;
#pragma unroll
        for (int ks = 0; ks < 4; ks++) {
            int kbyte = ks * 32 + lkh * 2;
            uint32_t a[2][4], bh[4][4];
#pragma unroll
            for (int mt = 0; mt < 2; mt++) {
                uint32_t off = SWZ128((wm * 32 + mt * 16 + lrow) * 128 + kbyte);
                ldsm4(a[mt][0], a[mt][1], a[mt][2], a[mt][3], st + off);
            }
#pragma unroll
            for (int nt = 0; nt < 4; nt++) {
                uint32_t off = SWZ128((wn * 64 + nt * 16 + lrow) * 128 + kbyte);
                ldsm4(bh[nt][0], bh[nt][1], bh[nt][2], bh[nt][3], st + 16384 + off);
            }
#pragma unroll
            for (int mt = 0; mt < 2; mt++)
#pragma unroll
                for (int nt = 0; nt < 4; nt++) {
                    mma16816(acc[mt][nt * 2],     a[mt], bh[nt][0], bh[nt][2]);
                    mma16816(acc[mt][nt * 2 + 1], a[mt], bh[nt][1], bh[nt][3]);
                }
        }
        __syncthreads();
    }

    // ---- epilogue ----
    int colb = (lane & 3) * 2;
#pragma unroll
    for (int mt = 0; mt < 2; mt++) {
        int rA = row0 + wm * 32 + mt * 16 + (lane >> 2);
        int rB = rA + 8;
        int tokA = 0, tokB = 0;
        if (mode == 2) { tokA = g_perm[rA]; tokB = g_perm[rB]; }
#pragma unroll
        for (int nf = 0; nf < 8; nf++) {
            int col = n0 + wn * 64 + nf * 8 + colb;
            float bi0 = bias[(size_t)e * N_TOT + col];
            float bi1 = bias[(size_t)e * N_TOT + col + 1];
            float vA0 = acc[mt][nf][0] + bi0, vA1 = acc[mt][nf][1] + bi1;
            float vB0 = acc[mt][nf][2] + bi0, vB1 = acc[mt][nf][3] + bi1;
            if (mode == 1) {
                __half2 hA, hB;
                hA.x = __float2half(gelu_exact(vA0));
                hA.y = __float2half(gelu_exact(vA1));
                hB.x = __float2half(gelu_exact(vB0));
                hB.y = __float2half(gelu_exact(vB1));
                *reinterpret_cast<__half2*>(g_H + (size_t)rA * DFF + col) = hA;
                *reinterpret_cast<__half2*>(g_H + (size_t)rB * DFF + col) = hB;
            } else {
                if (tokA < TOK)
                    *reinterpret_cast<float2*>(out + (size_t)tokA * DIM + col) =
                        make_float2(vA0, vA1);
                if (tokB < TOK)
                    *reinterpret_cast<float2*>(out + (size_t)tokB * DIM + col) =
                        make_float2(vB0, vB1);
            }
        }
    }
}

// ---------------- launch (single stream; no events — graph-capture safe) ----
extern "C" void kernel_launch(void* const* d_in, const int* in_sizes, int n_in,
                              void* d_out, int out_size)
{
    const float* x     = (const float*)d_in[0];
    const float* noise = (const float*)d_in[1];
    const float* rw    = (const float*)d_in[2];
    const float* rb    = (const float*)d_in[3];
    const float* w1    = (const float*)d_in[4];
    const float* b1    = (const float*)d_in[5];
    const float* w2    = (const float*)d_in[6];
    const float* b2    = (const float*)d_in[7];
    float* out = (float*)d_out;

    static __half *p_W1, *p_W2, *p_Ag, *p_H;
    static bool resolved = false;
    if (!resolved) {
        cudaGetSymbolAddress((void**)&p_W1, g_W1);
        cudaGetSymbolAddress((void**)&p_W2, g_W2);
        cudaGetSymbolAddress((void**)&p_Ag, g_Ag);
        cudaGetSymbolAddress((void**)&p_H, g_H);
        cudaFuncSetAttribute(gemm_kernel,
                             cudaFuncAttributeMaxDynamicSharedMemorySize, SMEM_REQ);
        resolved = true;
    }

    // prep: W1 convert + router in one fat launch
    init_kernel<<<1, 32>>>();
    prep_kernel<<<NB_CVT1 + NB_ROUT, 256>>>(x, noise, rw, rb, w1, p_W1);

    // routing chain
    rank_kernel<<<NEXP, 512>>>();
    finalize_kernel<<<TOK / 256, 256>>>();
    offsets_kernel<<<1, 32>>>();
    perminit_kernel<<<(PADMAX + 255) / 256, 256>>>();
    place_kernel<<<TOK / 256, 256>>>();
    gather_kernel<<<PADMAX + TOK / 256, 256>>>(x, out);

    // FFN pass 1 (+ W2 convert riding along): H = gelu(Xg @ W1^T + b1)
    gemm_kernel<<<dim3(DFF / 128, MAXROWTILES + CVT2_YEXT), 256, SMEM_REQ>>>(
        p_Ag, p_W1, b1, nullptr, DIM, DFF, 1, w2, p_W2);

    // FFN pass 2: out = H @ W2^T + b2 (scatter)   K=4096, N=1024
    gemm_kernel<<<dim3(DIM / 128, MAXROWTILES), 256, SMEM_REQ>>>(
        p_H, p_W2, b2, out, DFF, DIM, 2, nullptr, nullptr);
}

// round 10
// speedup vs baseline: 1.0422x; 1.0422x over previous
#include <cuda_runtime.h>
#include <cuda_fp16.h>
#include <math.h>
#include <stdint.h>

// ---------------- problem constants ----------------
#define TOK   16384
#define DIM   1024
#define DFF   4096
#define NEXP  8
#define CAP   3277
#define TM    128
#define PADMAX (TOK + NEXP*TM)          // 17408
#define MAXROWTILES (PADMAX/TM)         // 136
#define KC    64                         // K chunk (fp16 elems)
#define STAGE 32768                      // A 16K + B 16K
#define NSTAGE 3
#define SMEM_REQ (NSTAGE*STAGE + 1024)   // 99328; x2 CTAs = 198656 <= 227KB
#define NB_ROUT (TOK/8)                  // 2048 router blocks (8 warps = 8 tokens)
#define NB_CVT  2048                     // blocks per weight tensor (16 tiles each)

// ---------------- device scratch ----------------
__device__ unsigned char g_selmask[TOK];
__device__ signed char   g_final[TOK];
__device__ int g_off[NEXP + 1];
__device__ int g_perm[PADMAX];
__device__ __half g_Ag[(size_t)PADMAX * DIM];        // gathered x, fp16
__device__ __half g_H [(size_t)PADMAX * DFF];        // gelu intermediate, fp16
__device__ __half g_W1[(size_t)NEXP * DFF * DIM];    // W1^T fp16
__device__ __half g_W2[(size_t)NEXP * DIM * DFF];    // W2^T fp16

// ---------------- helpers ----------------
__device__ __forceinline__ uint32_t smem_u32(const void* p) {
    return (uint32_t)__cvta_generic_to_shared(p);
}
#define SWZ128(o) ((o) ^ (((o) >> 3) & 0x70))

#define CP16(dst, src) \
    asm volatile("cp.async.cg.shared.global [%0], [%1], 16;" :: "r"(dst), "l"(src) : "memory")
#define CP_COMMIT() asm volatile("cp.async.commit_group;" ::: "memory")
#define CP_WAIT1()  asm volatile("cp.async.wait_group 1;" ::: "memory")

__device__ __forceinline__ void ldsm4(uint32_t& r0, uint32_t& r1, uint32_t& r2,
                                      uint32_t& r3, uint32_t addr) {
    asm volatile("ldmatrix.sync.aligned.m8n8.x4.shared.b16 {%0,%1,%2,%3}, [%4];"
                 : "=r"(r0), "=r"(r1), "=r"(r2), "=r"(r3) : "r"(addr));
}

__device__ __forceinline__ void mma16816(float* c, const uint32_t* a,
                                         uint32_t b0, uint32_t b1) {
    asm volatile(
        "mma.sync.aligned.m16n8k16.row.col.f32.f16.f16.f32 "
        "{%0,%1,%2,%3}, {%4,%5,%6,%7}, {%8,%9}, {%0,%1,%2,%3};"
        : "+f"(c[0]), "+f"(c[1]), "+f"(c[2]), "+f"(c[3])
        : "r"(a[0]), "r"(a[1]), "r"(a[2]), "r"(a[3]), "r"(b0), "r"(b1));
}

__device__ __forceinline__ float gelu_exact(float v) {
    return 0.5f * v * (1.0f + erff(v * 0.70710678118654752f));
}

// transpose+convert one 32x32 tile: src fp32 [R rows, C cols]
// -> dst fp16 [C rows, R cols]; tsh = 32x33 float scratch (256 threads)
__device__ __forceinline__ void cvt_tile(const float* __restrict__ s,
                                         __half* __restrict__ d,
                                         float* tsh, int R, int C,
                                         int r0, int c0, int tx, int ty)
{
#pragma unroll
    for (int i = 0; i < 4; i++)
        tsh[(ty + i * 8) * 33 + tx] = s[(size_t)(r0 + ty + i * 8) * C + c0 + tx];
    __syncthreads();
#pragma unroll
    for (int i = 0; i < 4; i++) {
        int orow = c0 + ty + i * 8;
        int ocol = r0 + tx;
        d[(size_t)orow * R + ocol] = __float2half(tsh[tx * 33 + ty + i * 8]);
    }
    __syncthreads();
}

// ---------------- prep: router + both weight conversions, one launch -------
// blocks [0, NB_ROUT): router, warp-per-token (8 tokens/block)
// blocks [NB_ROUT, NB_ROUT+NB_CVT): W1 convert (16 tiles each)
// blocks [NB_ROUT+NB_CVT, NB_ROUT+2*NB_CVT): W2 convert (16 tiles each)
__global__ __launch_bounds__(256) void prep_kernel(
    const float* __restrict__ x, const float* __restrict__ noise,
    const float* __restrict__ rw, const float* __restrict__ rb,
    const float* __restrict__ w1, __half* __restrict__ w1dst,
    const float* __restrict__ w2, __half* __restrict__ w2dst)
{
    __shared__ float sh[32 * 33];
    int bid = blockIdx.x;
    int tid = threadIdx.x;

    if (bid < NB_ROUT) {
        int wid = tid >> 5, lane = tid & 31;
        int t = bid * 8 + wid;
        const float4* xr4 = reinterpret_cast<const float4*>(x + (size_t)t * DIM);
        const float4* rw4 = reinterpret_cast<const float4*>(rw);
        float acc[NEXP];
#pragma unroll
        for (int e = 0; e < NEXP; e++) acc[e] = 0.f;
#pragma unroll
        for (int i = 0; i < 8; i++) {          // DIM/4/32 = 8 float4 per lane
            int idx = i * 32 + lane;
            float4 xv = xr4[idx];
#pragma unroll
            for (int e = 0; e < NEXP; e++) {
                float4 wv = rw4[e * 256 + idx];
                acc[e] += xv.x * wv.x + xv.y * wv.y + xv.z * wv.z + xv.w * wv.w;
            }
        }
#pragma unroll
        for (int o = 16; o > 0; o >>= 1)
#pragma unroll
            for (int e = 0; e < NEXP; e++)
                acc[e] += __shfl_xor_sync(0xFFFFFFFFu, acc[e], o);
        if (lane == 0) {
            float lg[NEXP];
#pragma unroll
            for (int e = 0; e < NEXP; e++)
                lg[e] = acc[e] + rb[e] + noise[t * NEXP + e] * 0.02f;
            int e1 = 0;
#pragma unroll
            for (int e = 1; e < NEXP; e++) if (lg[e] > lg[e1]) e1 = e;
            int e2 = -1;
#pragma unroll
            for (int e = 0; e < NEXP; e++) {
                if (e == e1) continue;
                if (e2 < 0 || lg[e] > lg[e2]) e2 = e;
            }
            g_selmask[t] = (unsigned char)((1 << e1) | (1 << e2));
        }
        return;
    }

    int tx = tid & 31, ty = tid >> 5;
    if (bid < NB_ROUT + NB_CVT) {
        // W1: fp32 [E, DIM, DFF] -> fp16 [E, DFF, DIM]; tiles 32x128 per expert
        int cb = bid - NB_ROUT;
#pragma unroll 1
        for (int it = 0; it < 16; it++) {
            int g = cb * 16 + it;              // 0..32767
            int e = g >> 12;                   // 4096 tiles per expert
            int rem = g & 4095;
            int tr = rem & 31;                 // DIM/32 row tiles
            int tc = rem >> 5;                 // DFF/32 col tiles
            cvt_tile(w1 + (size_t)e * DIM * DFF, w1dst + (size_t)e * DFF * DIM,
                     sh, DIM, DFF, tr * 32, tc * 32, tx, ty);
        }
        return;
    }
    // W2: fp32 [E, DFF, DIM] -> fp16 [E, DIM, DFF]; tiles 128x32 per expert
    int cb = bid - NB_ROUT - NB_CVT;
#pragma unroll 1
    for (int it = 0; it < 16; it++) {
        int g = cb * 16 + it;
        int e = g >> 12;
        int rem = g & 4095;
        int tr = rem & 127;                    // DFF/32 row tiles
        int tc = rem >> 7;                     // DIM/32 col tiles
        cvt_tile(w2 + (size_t)e * DFF * DIM, w2dst + (size_t)e * DIM * DFF,
                 sh, DFF, DIM, tr * 32, tc * 32, tx, ty);
    }
}

// ---------------- route: rank+finalize+offsets+place+padinit in ONE block --
// 1024 threads; each owns 16 tokens. Two packed-uint64 scans (16b/expert lane).
__global__ __launch_bounds__(1024) void route_kernel()
{
    __shared__ uint64_t s0[1024], s1[1024];
    __shared__ int sF[NEXP], sOff[NEXP + 1];
    int tid = threadIdx.x;

    union { uint4 q; unsigned char b[16]; } u;
    u.q = reinterpret_cast<const uint4*>(g_selmask)[tid];
    uint32_t m[NEXP];
#pragma unroll
    for (int e = 0; e < NEXP; e++) m[e] = 0;
#pragma unroll
    for (int j = 0; j < 16; j++) {
        unsigned char sm = u.b[j];
#pragma unroll
        for (int e = 0; e < NEXP; e++)
            m[e] |= (uint32_t)((sm >> e) & 1) << j;
    }
    int cnt[NEXP];
#pragma unroll
    for (int e = 0; e < NEXP; e++) cnt[e] = __popc(m[e]);

    // scan 1: selection counts (capacity ranks)
    uint64_t p0 = (uint64_t)cnt[0] | ((uint64_t)cnt[1] << 16) |
                  ((uint64_t)cnt[2] << 32) | ((uint64_t)cnt[3] << 48);
    uint64_t p1 = (uint64_t)cnt[4] | ((uint64_t)cnt[5] << 16) |
                  ((uint64_t)cnt[6] << 32) | ((uint64_t)cnt[7] << 48);
    s0[tid] = p0; s1[tid] = p1;
    __syncthreads();
    for (int off = 1; off < 1024; off <<= 1) {
        uint64_t a0 = (tid >= off) ? s0[tid - off] : 0;
        uint64_t a1 = (tid >= off) ? s1[tid - off] : 0;
        __syncthreads();
        s0[tid] += a0; s1[tid] += a1;
        __syncthreads();
    }
    uint64_t i0 = s0[tid], i1 = s1[tid];
    int base[NEXP];
#pragma unroll
    for (int e = 0; e < 4; e++)
        base[e] = (int)((i0 >> (16 * e)) & 0xFFFF) - cnt[e];
#pragma unroll
    for (int e = 4; e < NEXP; e++)
        base[e] = (int)((i1 >> (16 * (e - 4))) & 0xFFFF) - cnt[e];

    // final expert per token: highest e among top-2 that kept it
    union { int4 q; signed char c[16]; } fo;
    uint32_t fm[NEXP];
#pragma unroll
    for (int e = 0; e < NEXP; e++) fm[e] = 0;
#pragma unroll
    for (int j = 0; j < 16; j++) {
        int f = -1;
#pragma unroll
        for (int e = NEXP - 1; e >= 0; e--) {
            if ((m[e] >> j) & 1) {
                int rank = base[e] + __popc(m[e] & ((1u << j) - 1u));
                if (rank < CAP) { f = e; break; }
            }
        }
        fo.c[j] = (signed char)f;
        if (f >= 0) fm[f] |= 1u << j;
    }
    reinterpret_cast<int4*>(g_final)[tid] = fo.q;

    // scan 2: final counts (placement)
    int fc[NEXP];
#pragma unroll
    for (int e = 0; e < NEXP; e++) fc[e] = __popc(fm[e]);
    uint64_t q0 = (uint64_t)fc[0] | ((uint64_t)fc[1] << 16) |
                  ((uint64_t)fc[2] << 32) | ((uint64_t)fc[3] << 48);
    uint64_t q1 = (uint64_t)fc[4] | ((uint64_t)fc[5] << 16) |
                  ((uint64_t)fc[6] << 32) | ((uint64_t)fc[7] << 48);
    __syncthreads();
    s0[tid] = q0; s1[tid] = q1;
    __syncthreads();
    for (int off = 1; off < 1024; off <<= 1) {
        uint64_t a0 = (tid >= off) ? s0[tid - off] : 0;
        uint64_t a1 = (tid >= off) ? s1[tid - off] : 0;
        __syncthreads();
        s0[tid] += a0; s1[tid] += a1;
        __syncthreads();
    }
    uint64_t j0 = s0[tid], j1 = s1[tid];
    int fbase[NEXP];
#pragma unroll
    for (int e = 0; e < 4; e++)
        fbase[e] = (int)((j0 >> (16 * e)) & 0xFFFF) - fc[e];
#pragma unroll
    for (int e = 4; e < NEXP; e++)
        fbase[e] = (int)((j1 >> (16 * (e - 4))) & 0xFFFF) - fc[e];

    if (tid == 1023) {
        int o = 0;
        sOff[0] = 0;
        for (int e = 0; e < NEXP; e++) {
            int F = (e < 4) ? (int)((j0 >> (16 * e)) & 0xFFFF)
                            : (int)((j1 >> (16 * (e - 4))) & 0xFFFF);
            sF[e] = F;
            o += ((F + TM - 1) / TM) * TM;
            sOff[e + 1] = o;
        }
    }
    __syncthreads();
    if (tid <= NEXP) g_off[tid] = sOff[tid];

    // deterministic placement
#pragma unroll
    for (int j = 0; j < 16; j++) {
        int f = fo.c[j];
        if (f >= 0) {
            int pos = sOff[f] + fbase[f] + __popc(fm[f] & ((1u << j) - 1u));
            g_perm[pos] = tid * 16 + j;
        }
    }
    // pad slots -> sentinel
    for (int e = 0; e < NEXP; e++)
        for (int i = sOff[e] + sF[e] + tid; i < sOff[e + 1]; i += 1024)
            g_perm[i] = TOK;
}

// fat gather: blocks [0,PADMAX) gather x rows by g_perm (fp16);
// blocks [PADMAX, PADMAX+64) zero dropped-token output rows.
__global__ __launch_bounds__(256) void gather_kernel(
    const float* __restrict__ x, float* __restrict__ out)
{
    int bid = blockIdx.x;
    int tid = threadIdx.x;
    if (bid < PADMAX) {
        int tok = g_perm[bid];
        float4 v = make_float4(0.f, 0.f, 0.f, 0.f);
        if (tok < TOK)
            v = reinterpret_cast<const float4*>(x + (size_t)tok * DIM)[tid];
        __half h[4];
        h[0] = __float2half(v.x); h[1] = __float2half(v.y);
        h[2] = __float2half(v.z); h[3] = __float2half(v.w);
        reinterpret_cast<uint2*>(g_Ag + (size_t)bid * DIM)[tid] =
            *reinterpret_cast<uint2*>(h);
        return;
    }
    __shared__ int list[256];
    __shared__ int cnt;
    if (tid == 0) cnt = 0;
    __syncthreads();
    int t = (bid - PADMAX) * 256 + tid;
    if (g_final[t] < 0) { int p = atomicAdd(&cnt, 1); list[p] = t; }
    __syncthreads();
    float4 z = make_float4(0.f, 0.f, 0.f, 0.f);
    for (int i = 0; i < cnt; i++) {
        size_t row = (size_t)list[i] * DIM;
        reinterpret_cast<float4*>(out + row)[tid] = z;  // 256*4 = 1024
    }
}

// ---------------- HMMA GEMM (both FFN passes) — proven R8 version ----------
// D[128x128] = A[128 x K] * B^T, B: [N_TOT x K] row-major (k contiguous).
// single fp16 term, fp32 accum. 3-stage cp.async pipeline, 2 CTAs/SM.
// mode 1: +b1 -> gelu -> fp16 -> g_H
// mode 2: +b2 -> scatter fp32 rows to out[token]
__global__ __launch_bounds__(256, 2) void gemm_kernel(
    const __half* __restrict__ A, const __half* __restrict__ B,
    const float* __restrict__ bias, float* __restrict__ out,
    int K_TOT, int N_TOT, int mode)
{
    int row0 = blockIdx.y * TM;
    if (row0 >= g_off[NEXP]) return;
    int e = 0;
#pragma unroll
    for (int i = 0; i < NEXP; i++) if (row0 >= g_off[i + 1]) e = i + 1;
    int n0 = blockIdx.x * 128;

    extern __shared__ __align__(1024) char smem_raw[];
    uint32_t sb = (smem_u32(smem_raw) + 1023) & ~1023u;

    int tid = threadIdx.x;
    int lane = tid & 31;
    int wid = tid >> 5;
    int wm = wid & 3;          // warp m position (4 x 32 rows)
    int wn = wid >> 2;         // warp n position (2 x 64 cols)
    int lrow = (lane & 7) + ((lane >> 3) & 1) * 8;
    int lkh  = (lane >> 4) * 8;

    const size_t eN = (size_t)e * N_TOT;
    const int C = K_TOT >> 6;

    auto fill_stage = [&](int s, int c) {
        uint32_t st = sb + s * STAGE;
        int k0 = c * KC;
#pragma unroll
        for (int j = 0; j < 4; j++) {
            int u = tid + j * 256;
            int row = u >> 3, kp = u & 7;
            uint32_t so = SWZ128(row * 128 + kp * 16);
            size_t gi = (size_t)(row0 + row) * K_TOT + k0 + kp * 8;
            CP16(st + so, (const char*)(A + gi));
            size_t gb = (eN + n0 + row) * K_TOT + k0 + kp * 8;
            CP16(st + 16384 + so, (const char*)(B + gb));
        }
    };

    float acc[2][8][4];
#pragma unroll
    for (int mt = 0; mt < 2; mt++)
#pragma unroll
        for (int nf = 0; nf < 8; nf++)
#pragma unroll
            for (int q = 0; q < 4; q++) acc[mt][nf][q] = 0.f;

    fill_stage(0, 0); CP_COMMIT();
    fill_stage(1, 1); CP_COMMIT();

    for (int c = 0; c < C; ++c) {
        int s = c % 3;
        CP_WAIT1();
        __syncthreads();
        if (c + 2 < C) fill_stage((c + 2) % 3, c + 2);
        CP_COMMIT();
        uint32_t st = sb + s * STAGE;
#pragma unroll
        for (int ks = 0; ks < 4; ks++) {
            int kbyte = ks * 32 + lkh * 2;
            uint32_t a[2][4], bh[4][4];
#pragma unroll
            for (int mt = 0; mt < 2; mt++) {
                uint32_t off = SWZ128((wm * 32 + mt * 16 + lrow) * 128 + kbyte);
                ldsm4(a[mt][0], a[mt][1], a[mt][2], a[mt][3], st + off);
            }
#pragma unroll
            for (int nt = 0; nt < 4; nt++) {
                uint32_t off = SWZ128((wn * 64 + nt * 16 + lrow) * 128 + kbyte);
                ldsm4(bh[nt][0], bh[nt][1], bh[nt][2], bh[nt][3], st + 16384 + off);
            }
#pragma unroll
            for (int mt = 0; mt < 2; mt++)
#pragma unroll
                for (int nt = 0; nt < 4; nt++) {
                    mma16816(acc[mt][nt * 2],     a[mt], bh[nt][0], bh[nt][2]);
                    mma16816(acc[mt][nt * 2 + 1], a[mt], bh[nt][1], bh[nt][3]);
                }
        }
        __syncthreads();
    }

    int colb = (lane & 3) * 2;
#pragma unroll
    for (int mt = 0; mt < 2; mt++) {
        int rA = row0 + wm * 32 + mt * 16 + (lane >> 2);
        int rB = rA + 8;
        int tokA = 0, tokB = 0;
        if (mode == 2) { tokA = g_perm[rA]; tokB = g_perm[rB]; }
#pragma unroll
        for (int nf = 0; nf < 8; nf++) {
            int col = n0 + wn * 64 + nf * 8 + colb;
            float bi0 = bias[(size_t)e * N_TOT + col];
            float bi1 = bias[(size_t)e * N_TOT + col + 1];
            float vA0 = acc[mt][nf][0] + bi0, vA1 = acc[mt][nf][1] + bi1;
            float vB0 = acc[mt][nf][2] + bi0, vB1 = acc[mt][nf][3] + bi1;
            if (mode == 1) {
                __half2 hA, hB;
                hA.x = __float2half(gelu_exact(vA0));
                hA.y = __float2half(gelu_exact(vA1));
                hB.x = __float2half(gelu_exact(vB0));
                hB.y = __float2half(gelu_exact(vB1));
                *reinterpret_cast<__half2*>(g_H + (size_t)rA * DFF + col) = hA;
                *reinterpret_cast<__half2*>(g_H + (size_t)rB * DFF + col) = hB;
            } else {
                if (tokA < TOK)
                    *reinterpret_cast<float2*>(out + (size_t)tokA * DIM + col) =
                        make_float2(vA0, vA1);
                if (tokB < TOK)
                    *reinterpret_cast<float2*>(out + (size_t)tokB * DIM + col) =
                        make_float2(vB0, vB1);
            }
        }
    }
}

// ---------------- launch (single stream; no events — graph-capture safe) ----
extern "C" void kernel_launch(void* const* d_in, const int* in_sizes, int n_in,
                              void* d_out, int out_size)
{
    const float* x     = (const float*)d_in[0];
    const float* noise = (const float*)d_in[1];
    const float* rw    = (const float*)d_in[2];
    const float* rb    = (const float*)d_in[3];
    const float* w1    = (const float*)d_in[4];
    const float* b1    = (const float*)d_in[5];
    const float* w2    = (const float*)d_in[6];
    const float* b2    = (const float*)d_in[7];
    float* out = (float*)d_out;

    static __half *p_W1, *p_W2, *p_Ag, *p_H;
    static bool resolved = false;
    if (!resolved) {
        cudaGetSymbolAddress((void**)&p_W1, g_W1);
        cudaGetSymbolAddress((void**)&p_W2, g_W2);
        cudaGetSymbolAddress((void**)&p_Ag, g_Ag);
        cudaGetSymbolAddress((void**)&p_H, g_H);
        cudaFuncSetAttribute(gemm_kernel,
                             cudaFuncAttributeMaxDynamicSharedMemorySize, SMEM_REQ);
        resolved = true;
    }

    // 1: router + W1 convert + W2 convert (one fat, small-smem launch)
    prep_kernel<<<NB_ROUT + 2 * NB_CVT, 256>>>(x, noise, rw, rb,
                                               w1, p_W1, w2, p_W2);
    // 2: full routing resolution in one block
    route_kernel<<<1, 1024>>>();
    // 3: gather + zero-dropped
    gather_kernel<<<PADMAX + TOK / 256, 256>>>(x, out);

    // 4: FFN pass 1: H = gelu(Xg @ W1^T + b1)   K=1024, N=4096
    gemm_kernel<<<dim3(DFF / 128, MAXROWTILES), 256, SMEM_REQ>>>(
        p_Ag, p_W1, b1, nullptr, DIM, DFF, 1);

    // 5: FFN pass 2: out = H @ W2^T + b2 (scatter)   K=4096, N=1024
    gemm_kernel<<<dim3(DIM / 128, MAXROWTILES), 256, SMEM_REQ>>>(
        p_H, p_W2, b2, out, DFF, DIM, 2);
}

// round 11
// speedup vs baseline: 1.0623x; 1.0192x over previous
#include <cuda_runtime.h>
#include <cuda_fp16.h>
#include <math.h>
#include <stdint.h>

// ---------------- problem constants ----------------
#define TOK   16384
#define DIM   1024
#define DFF   4096
#define NEXP  8
#define CAP   3277
#define TM    128
#define PADMAX (TOK + NEXP*TM)          // 17408
#define MAXROWTILES (PADMAX/TM)         // 136
#define KC    64                         // K chunk (fp16 elems)
#define STAGE 32768                      // A 16K + B 16K
#define NSTAGE 3
#define SMEM_REQ (NSTAGE*STAGE + 1024)   // 99328; x2 CTAs = 198656 <= 227KB
#define NB_ROUT (TOK/8)                  // 2048 router blocks (8 warps = 8 tokens)
#define NB_CVT  2048                     // blocks per weight tensor (16 tiles each)

// ---------------- device scratch ----------------
__device__ unsigned char g_selmask[TOK];
__device__ signed char   g_final[TOK];
__device__ int g_off[NEXP + 1];
__device__ int g_perm[PADMAX];
__device__ __half g_Ag[(size_t)PADMAX * DIM];        // gathered x, fp16
__device__ __half g_H [(size_t)PADMAX * DFF];        // gelu intermediate, fp16
__device__ __half g_W1[(size_t)NEXP * DFF * DIM];    // W1^T fp16
__device__ __half g_W2[(size_t)NEXP * DIM * DFF];    // W2^T fp16

// ---------------- helpers ----------------
__device__ __forceinline__ uint32_t smem_u32(const void* p) {
    return (uint32_t)__cvta_generic_to_shared(p);
}
#define SWZ128(o) ((o) ^ (((o) >> 3) & 0x70))

#define CP16(dst, src) \
    asm volatile("cp.async.cg.shared.global [%0], [%1], 16;" :: "r"(dst), "l"(src) : "memory")
#define CP_COMMIT() asm volatile("cp.async.commit_group;" ::: "memory")
#define CP_WAIT1()  asm volatile("cp.async.wait_group 1;" ::: "memory")

__device__ __forceinline__ void ldsm4(uint32_t& r0, uint32_t& r1, uint32_t& r2,
                                      uint32_t& r3, uint32_t addr) {
    asm volatile("ldmatrix.sync.aligned.m8n8.x4.shared.b16 {%0,%1,%2,%3}, [%4];"
                 : "=r"(r0), "=r"(r1), "=r"(r2), "=r"(r3) : "r"(addr));
}

__device__ __forceinline__ void mma16816(float* c, const uint32_t* a,
                                         uint32_t b0, uint32_t b1) {
    asm volatile(
        "mma.sync.aligned.m16n8k16.row.col.f32.f16.f16.f32 "
        "{%0,%1,%2,%3}, {%4,%5,%6,%7}, {%8,%9}, {%0,%1,%2,%3};"
        : "+f"(c[0]), "+f"(c[1]), "+f"(c[2]), "+f"(c[3])
        : "r"(a[0]), "r"(a[1]), "r"(a[2]), "r"(a[3]), "r"(b0), "r"(b1));
}

__device__ __forceinline__ float gelu_exact(float v) {
    return 0.5f * v * (1.0f + erff(v * 0.70710678118654752f));
}

// transpose+convert one 32x32 tile: src fp32 [R rows, C cols]
// -> dst fp16 [C rows, R cols]; tsh = 32x33 float scratch (256 threads)
__device__ __forceinline__ void cvt_tile(const float* __restrict__ s,
                                         __half* __restrict__ d,
                                         float* tsh, int R, int C,
                                         int r0, int c0, int tx, int ty)
{
#pragma unroll
    for (int i = 0; i < 4; i++)
        tsh[(ty + i * 8) * 33 + tx] = s[(size_t)(r0 + ty + i * 8) * C + c0 + tx];
    __syncthreads();
#pragma unroll
    for (int i = 0; i < 4; i++) {
        int orow = c0 + ty + i * 8;
        int ocol = r0 + tx;
        d[(size_t)orow * R + ocol] = __float2half(tsh[tx * 33 + ty + i * 8]);
    }
    __syncthreads();
}

// ---------------- prep: router + both weight conversions, one launch -------
__global__ __launch_bounds__(256) void prep_kernel(
    const float* __restrict__ x, const float* __restrict__ noise,
    const float* __restrict__ rw, const float* __restrict__ rb,
    const float* __restrict__ w1, __half* __restrict__ w1dst,
    const float* __restrict__ w2, __half* __restrict__ w2dst)
{
    __shared__ float sh[32 * 33];
    int bid = blockIdx.x;
    int tid = threadIdx.x;

    if (bid < NB_ROUT) {
        int wid = tid >> 5, lane = tid & 31;
        int t = bid * 8 + wid;
        const float4* xr4 = reinterpret_cast<const float4*>(x + (size_t)t * DIM);
        const float4* rw4 = reinterpret_cast<const float4*>(rw);
        float acc[NEXP];
#pragma unroll
        for (int e = 0; e < NEXP; e++) acc[e] = 0.f;
#pragma unroll
        for (int i = 0; i < 8; i++) {          // DIM/4/32 = 8 float4 per lane
            int idx = i * 32 + lane;
            float4 xv = xr4[idx];
#pragma unroll
            for (int e = 0; e < NEXP; e++) {
                float4 wv = rw4[e * 256 + idx];
                acc[e] += xv.x * wv.x + xv.y * wv.y + xv.z * wv.z + xv.w * wv.w;
            }
        }
#pragma unroll
        for (int o = 16; o > 0; o >>= 1)
#pragma unroll
            for (int e = 0; e < NEXP; e++)
                acc[e] += __shfl_xor_sync(0xFFFFFFFFu, acc[e], o);
        if (lane == 0) {
            float lg[NEXP];
#pragma unroll
            for (int e = 0; e < NEXP; e++)
                lg[e] = acc[e] + rb[e] + noise[t * NEXP + e] * 0.02f;
            int e1 = 0;
#pragma unroll
            for (int e = 1; e < NEXP; e++) if (lg[e] > lg[e1]) e1 = e;
            int e2 = -1;
#pragma unroll
            for (int e = 0; e < NEXP; e++) {
                if (e == e1) continue;
                if (e2 < 0 || lg[e] > lg[e2]) e2 = e;
            }
            g_selmask[t] = (unsigned char)((1 << e1) | (1 << e2));
        }
        return;
    }

    int tx = tid & 31, ty = tid >> 5;
    if (bid < NB_ROUT + NB_CVT) {
        int cb = bid - NB_ROUT;
#pragma unroll 1
        for (int it = 0; it < 16; it++) {
            int g = cb * 16 + it;
            int e = g >> 12;
            int rem = g & 4095;
            int tr = rem & 31;
            int tc = rem >> 5;
            cvt_tile(w1 + (size_t)e * DIM * DFF, w1dst + (size_t)e * DFF * DIM,
                     sh, DIM, DFF, tr * 32, tc * 32, tx, ty);
        }
        return;
    }
    int cb = bid - NB_ROUT - NB_CVT;
#pragma unroll 1
    for (int it = 0; it < 16; it++) {
        int g = cb * 16 + it;
        int e = g >> 12;
        int rem = g & 4095;
        int tr = rem & 127;
        int tc = rem >> 7;
        cvt_tile(w2 + (size_t)e * DFF * DIM, w2dst + (size_t)e * DIM * DFF,
                 sh, DFF, DIM, tr * 32, tc * 32, tx, ty);
    }
}

// ---------------- route: full routing resolution in one block --------------
__global__ __launch_bounds__(1024) void route_kernel()
{
    __shared__ uint64_t s0[1024], s1[1024];
    __shared__ int sF[NEXP], sOff[NEXP + 1];
    int tid = threadIdx.x;

    union { uint4 q; unsigned char b[16]; } u;
    u.q = reinterpret_cast<const uint4*>(g_selmask)[tid];
    uint32_t m[NEXP];
#pragma unroll
    for (int e = 0; e < NEXP; e++) m[e] = 0;
#pragma unroll
    for (int j = 0; j < 16; j++) {
        unsigned char sm = u.b[j];
#pragma unroll
        for (int e = 0; e < NEXP; e++)
            m[e] |= (uint32_t)((sm >> e) & 1) << j;
    }
    int cnt[NEXP];
#pragma unroll
    for (int e = 0; e < NEXP; e++) cnt[e] = __popc(m[e]);

    uint64_t p0 = (uint64_t)cnt[0] | ((uint64_t)cnt[1] << 16) |
                  ((uint64_t)cnt[2] << 32) | ((uint64_t)cnt[3] << 48);
    uint64_t p1 = (uint64_t)cnt[4] | ((uint64_t)cnt[5] << 16) |
                  ((uint64_t)cnt[6] << 32) | ((uint64_t)cnt[7] << 48);
    s0[tid] = p0; s1[tid] = p1;
    __syncthreads();
    for (int off = 1; off < 1024; off <<= 1) {
        uint64_t a0 = (tid >= off) ? s0[tid - off] : 0;
        uint64_t a1 = (tid >= off) ? s1[tid - off] : 0;
        __syncthreads();
        s0[tid] += a0; s1[tid] += a1;
        __syncthreads();
    }
    uint64_t i0 = s0[tid], i1 = s1[tid];
    int base[NEXP];
#pragma unroll
    for (int e = 0; e < 4; e++)
        base[e] = (int)((i0 >> (16 * e)) & 0xFFFF) - cnt[e];
#pragma unroll
    for (int e = 4; e < NEXP; e++)
        base[e] = (int)((i1 >> (16 * (e - 4))) & 0xFFFF) - cnt[e];

    union { int4 q; signed char c[16]; } fo;
    uint32_t fm[NEXP];
#pragma unroll
    for (int e = 0; e < NEXP; e++) fm[e] = 0;
#pragma unroll
    for (int j = 0; j < 16; j++) {
        int f = -1;
#pragma unroll
        for (int e = NEXP - 1; e >= 0; e--) {
            if ((m[e] >> j) & 1) {
                int rank = base[e] + __popc(m[e] & ((1u << j) - 1u));
                if (rank < CAP) { f = e; break; }
            }
        }
        fo.c[j] = (signed char)f;
        if (f >= 0) fm[f] |= 1u << j;
    }
    reinterpret_cast<int4*>(g_final)[tid] = fo.q;

    int fc[NEXP];
#pragma unroll
    for (int e = 0; e < NEXP; e++) fc[e] = __popc(fm[e]);
    uint64_t q0 = (uint64_t)fc[0] | ((uint64_t)fc[1] << 16) |
                  ((uint64_t)fc[2] << 32) | ((uint64_t)fc[3] << 48);
    uint64_t q1 = (uint64_t)fc[4] | ((uint64_t)fc[5] << 16) |
                  ((uint64_t)fc[6] << 32) | ((uint64_t)fc[7] << 48);
    __syncthreads();
    s0[tid] = q0; s1[tid] = q1;
    __syncthreads();
    for (int off = 1; off < 1024; off <<= 1) {
        uint64_t a0 = (tid >= off) ? s0[tid - off] : 0;
        uint64_t a1 = (tid >= off) ? s1[tid - off] : 0;
        __syncthreads();
        s0[tid] += a0; s1[tid] += a1;
        __syncthreads();
    }
    uint64_t j0 = s0[tid], j1 = s1[tid];
    int fbase[NEXP];
#pragma unroll
    for (int e = 0; e < 4; e++)
        fbase[e] = (int)((j0 >> (16 * e)) & 0xFFFF) - fc[e];
#pragma unroll
    for (int e = 4; e < NEXP; e++)
        fbase[e] = (int)((j1 >> (16 * (e - 4))) & 0xFFFF) - fc[e];

    if (tid == 1023) {
        int o = 0;
        sOff[0] = 0;
        for (int e = 0; e < NEXP; e++) {
            int F = (e < 4) ? (int)((j0 >> (16 * e)) & 0xFFFF)
                            : (int)((j1 >> (16 * (e - 4))) & 0xFFFF);
            sF[e] = F;
            o += ((F + TM - 1) / TM) * TM;
            sOff[e + 1] = o;
        }
    }
    __syncthreads();
    if (tid <= NEXP) g_off[tid] = sOff[tid];

#pragma unroll
    for (int j = 0; j < 16; j++) {
        int f = fo.c[j];
        if (f >= 0) {
            int pos = sOff[f] + fbase[f] + __popc(fm[f] & ((1u << j) - 1u));
            g_perm[pos] = tid * 16 + j;
        }
    }
    for (int e = 0; e < NEXP; e++)
        for (int i = sOff[e] + sF[e] + tid; i < sOff[e + 1]; i += 1024)
            g_perm[i] = TOK;
}

// fat gather: gather + zero-dropped
__global__ __launch_bounds__(256) void gather_kernel(
    const float* __restrict__ x, float* __restrict__ out)
{
    int bid = blockIdx.x;
    int tid = threadIdx.x;
    if (bid < PADMAX) {
        int tok = g_perm[bid];
        float4 v = make_float4(0.f, 0.f, 0.f, 0.f);
        if (tok < TOK)
            v = reinterpret_cast<const float4*>(x + (size_t)tok * DIM)[tid];
        __half h[4];
        h[0] = __float2half(v.x); h[1] = __float2half(v.y);
        h[2] = __float2half(v.z); h[3] = __float2half(v.w);
        reinterpret_cast<uint2*>(g_Ag + (size_t)bid * DIM)[tid] =
            *reinterpret_cast<uint2*>(h);
        return;
    }
    __shared__ int list[256];
    __shared__ int cnt;
    if (tid == 0) cnt = 0;
    __syncthreads();
    int t = (bid - PADMAX) * 256 + tid;
    if (g_final[t] < 0) { int p = atomicAdd(&cnt, 1); list[p] = t; }
    __syncthreads();
    float4 z = make_float4(0.f, 0.f, 0.f, 0.f);
    for (int i = 0; i < cnt; i++) {
        size_t row = (size_t)list[i] * DIM;
        reinterpret_cast<float4*>(out + row)[tid] = z;
    }
}

// ---------------- HMMA GEMM — templated, ALU-stripped inner loop ----------
// D[128x128] = A[128 x KT] * B^T, B: [N_TOT x KT] row-major (k contiguous).
// Compile-time KT/NT/MODE; ldsm addresses via precomputed swizzle bases
// (addr_ks = base XOR (ks<<5), proven carry-free); fill via hoisted pointers.
template<int KT, int NT, int MODE>
__global__ __launch_bounds__(256, 2) void gemm_kernel(
    const __half* __restrict__ A, const __half* __restrict__ B,
    const float* __restrict__ bias, float* __restrict__ out)
{
    int row0 = blockIdx.y * TM;
    if (row0 >= g_off[NEXP]) return;
    int e = 0;
#pragma unroll
    for (int i = 0; i < NEXP; i++) if (row0 >= g_off[i + 1]) e = i + 1;
    int n0 = blockIdx.x * 128;

    extern __shared__ __align__(1024) char smem_raw[];
    uint32_t sb = (smem_u32(smem_raw) + 1023) & ~1023u;

    int tid = threadIdx.x;
    int lane = tid & 31;
    int wid = tid >> 5;
    int wm = wid & 3;          // warp m position (4 x 32 rows)
    int wn = wid >> 2;         // warp n position (2 x 64 cols)
    int lrow = (lane & 7) + ((lane >> 3) & 1) * 8;
    int lkh2 = ((lane >> 4) * 8) * 2;      // 0 or 16 bytes

    constexpr int C = KT >> 6;             // chunks of 64

    // ---- hoisted fill addressing ----
    // thread writes rows (tid>>3)+j*32, 16B at kp=(tid&7); smem offset stride
    // per j is +4096 (row&7 invariant -> swizzle-invariant)
    uint32_t so = SWZ128(((tid >> 3) << 7) + ((tid & 7) << 4));
    const __half* gA = A + (size_t)(row0 + (tid >> 3)) * KT + (tid & 7) * 8;
    const __half* gB = B + ((size_t)e * NT + n0 + (tid >> 3)) * KT + (tid & 7) * 8;

    auto fill_stage = [&](int s, int c) {
        uint32_t st = sb + s * STAGE + so;
        const __half* a = gA + c * KC;
        const __half* b = gB + c * KC;
#pragma unroll
        for (int j = 0; j < 4; j++) {
            CP16(st + j * 4096,         (const char*)(a + (size_t)j * 32 * KT));
            CP16(st + 16384 + j * 4096, (const char*)(b + (size_t)j * 32 * KT));
        }
    };

    // ---- precomputed ldsm swizzle bases (relative to stage base) ----
    uint32_t arel[2], brel[4];
#pragma unroll
    for (int mt = 0; mt < 2; mt++)
        arel[mt] = SWZ128(((wm * 32 + mt * 16 + lrow) << 7) + lkh2);
#pragma unroll
    for (int nt = 0; nt < 4; nt++)
        brel[nt] = 16384u + SWZ128(((wn * 64 + nt * 16 + lrow) << 7) + lkh2);

    float acc[2][8][4];
#pragma unroll
    for (int mt = 0; mt < 2; mt++)
#pragma unroll
        for (int nf = 0; nf < 8; nf++)
#pragma unroll
            for (int q = 0; q < 4; q++) acc[mt][nf][q] = 0.f;

    fill_stage(0, 0); CP_COMMIT();
    fill_stage(1, 1); CP_COMMIT();

#pragma unroll 1
    for (int c = 0; c < C; ++c) {
        int s = c % 3;
        CP_WAIT1();
        __syncthreads();
        if (c + 2 < C) fill_stage((c + 2) % 3, c + 2);
        CP_COMMIT();
        uint32_t st = sb + s * STAGE;
        uint32_t ab[2], bb[4];
#pragma unroll
        for (int mt = 0; mt < 2; mt++) ab[mt] = st + arel[mt];
#pragma unroll
        for (int nt = 0; nt < 4; nt++) bb[nt] = st + brel[nt];
#pragma unroll
        for (int ks = 0; ks < 4; ks++) {
            uint32_t kx = (uint32_t)ks << 5;
            uint32_t a[2][4], bh[4][4];
#pragma unroll
            for (int mt = 0; mt < 2; mt++)
                ldsm4(a[mt][0], a[mt][1], a[mt][2], a[mt][3], ab[mt] ^ kx);
#pragma unroll
            for (int nt = 0; nt < 4; nt++)
                ldsm4(bh[nt][0], bh[nt][1], bh[nt][2], bh[nt][3], bb[nt] ^ kx);
#pragma unroll
            for (int mt = 0; mt < 2; mt++)
#pragma unroll
                for (int nt = 0; nt < 4; nt++) {
                    mma16816(acc[mt][nt * 2],     a[mt], bh[nt][0], bh[nt][2]);
                    mma16816(acc[mt][nt * 2 + 1], a[mt], bh[nt][1], bh[nt][3]);
                }
        }
        __syncthreads();
    }

    // ---- epilogue ----
    int colb = (lane & 3) * 2;
#pragma unroll
    for (int mt = 0; mt < 2; mt++) {
        int rA = row0 + wm * 32 + mt * 16 + (lane >> 2);
        int rB = rA + 8;
        int tokA = 0, tokB = 0;
        if (MODE == 2) { tokA = g_perm[rA]; tokB = g_perm[rB]; }
#pragma unroll
        for (int nf = 0; nf < 8; nf++) {
            int col = n0 + wn * 64 + nf * 8 + colb;
            float bi0 = bias[(size_t)e * NT + col];
            float bi1 = bias[(size_t)e * NT + col + 1];
            float vA0 = acc[mt][nf][0] + bi0, vA1 = acc[mt][nf][1] + bi1;
            float vB0 = acc[mt][nf][2] + bi0, vB1 = acc[mt][nf][3] + bi1;
            if (MODE == 1) {
                __half2 hA, hB;
                hA.x = __float2half(gelu_exact(vA0));
                hA.y = __float2half(gelu_exact(vA1));
                hB.x = __float2half(gelu_exact(vB0));
                hB.y = __float2half(gelu_exact(vB1));
                *reinterpret_cast<__half2*>(g_H + (size_t)rA * DFF + col) = hA;
                *reinterpret_cast<__half2*>(g_H + (size_t)rB * DFF + col) = hB;
            } else {
                if (tokA < TOK)
                    *reinterpret_cast<float2*>(out + (size_t)tokA * DIM + col) =
                        make_float2(vA0, vA1);
                if (tokB < TOK)
                    *reinterpret_cast<float2*>(out + (size_t)tokB * DIM + col) =
                        make_float2(vB0, vB1);
            }
        }
    }
}

// ---------------- launch (single stream; no events — graph-capture safe) ----
extern "C" void kernel_launch(void* const* d_in, const int* in_sizes, int n_in,
                              void* d_out, int out_size)
{
    const float* x     = (const float*)d_in[0];
    const float* noise = (const float*)d_in[1];
    const float* rw    = (const float*)d_in[2];
    const float* rb    = (const float*)d_in[3];
    const float* w1    = (const float*)d_in[4];
    const float* b1    = (const float*)d_in[5];
    const float* w2    = (const float*)d_in[6];
    const float* b2    = (const float*)d_in[7];
    float* out = (float*)d_out;

    static __half *p_W1, *p_W2, *p_Ag, *p_H;
    static bool resolved = false;
    if (!resolved) {
        cudaGetSymbolAddress((void**)&p_W1, g_W1);
        cudaGetSymbolAddress((void**)&p_W2, g_W2);
        cudaGetSymbolAddress((void**)&p_Ag, g_Ag);
        cudaGetSymbolAddress((void**)&p_H, g_H);
        cudaFuncSetAttribute(gemm_kernel<DIM, DFF, 1>,
                             cudaFuncAttributeMaxDynamicSharedMemorySize, SMEM_REQ);
        cudaFuncSetAttribute(gemm_kernel<DFF, DIM, 2>,
                             cudaFuncAttributeMaxDynamicSharedMemorySize, SMEM_REQ);
        resolved = true;
    }

    // 1: router + W1 convert + W2 convert (one fat, small-smem launch)
    prep_kernel<<<NB_ROUT + 2 * NB_CVT, 256>>>(x, noise, rw, rb,
                                               w1, p_W1, w2, p_W2);
    // 2: full routing resolution in one block
    route_kernel<<<1, 1024>>>();
    // 3: gather + zero-dropped
    gather_kernel<<<PADMAX + TOK / 256, 256>>>(x, out);

    // 4: FFN pass 1: H = gelu(Xg @ W1^T + b1)   K=1024, N=4096
    gemm_kernel<DIM, DFF, 1><<<dim3(DFF / 128, MAXROWTILES), 256, SMEM_REQ>>>(
        p_Ag, p_W1, b1, nullptr);

    // 5: FFN pass 2: out = H @ W2^T + b2 (scatter)   K=4096, N=1024
    gemm_kernel<DFF, DIM, 2><<<dim3(DIM / 128, MAXROWTILES), 256, SMEM_REQ>>>(
        p_H, p_W2, b2, out);
}

// round 13
// speedup vs baseline: 1.0901x; 1.0262x over previous
#include <cuda_runtime.h>
#include <cuda_fp16.h>
#include <math.h>
#include <stdint.h>

// ---------------- problem constants ----------------
#define TOK   16384
#define DIM   1024
#define DFF   4096
#define NEXP  8
#define CAP   3277
#define TM    128
#define PADMAX (TOK + NEXP*TM)          // 17408
#define MAXROWTILES (PADMAX/TM)         // 136
#define KC    64                         // K chunk (fp16 elems)
#define STAGE 32768                      // A 16K + B 16K
#define NSTAGE 3
#define SMEM_REQ (NSTAGE*STAGE + 1024)   // 99328; x2 CTAs = 198656 <= 227KB
#define NB_ROUT (TOK/8)                  // 2048 router blocks (8 warps = 8 tokens)
#define NB_CVT  2048                     // blocks per weight tensor (16 tiles each)

// ---------------- device scratch ----------------
__device__ unsigned char g_selmask[TOK];
__device__ signed char   g_final[TOK];
__device__ int g_off[NEXP + 1];
__device__ int g_perm[PADMAX];
__device__ __half g_Ag[(size_t)PADMAX * DIM];        // gathered x, fp16
__device__ __half g_H [(size_t)PADMAX * DFF];        // gelu intermediate, fp16
__device__ __half g_W1[(size_t)NEXP * DFF * DIM];    // W1^T fp16
__device__ __half g_W2[(size_t)NEXP * DIM * DFF];    // W2^T fp16

// ---------------- helpers ----------------
__device__ __forceinline__ uint32_t smem_u32(const void* p) {
    return (uint32_t)__cvta_generic_to_shared(p);
}
#define SWZ128(o) ((o) ^ (((o) >> 3) & 0x70))

// cp.async with compile-time byte offsets on both addresses
#define CP16I(dst, src, DOF, SOF) \
    asm volatile("cp.async.cg.shared.global [%0+%2], [%1+%3], 16;" \
        :: "r"(dst), "l"(src), "n"(DOF), "n"(SOF) : "memory")
#define CP_COMMIT() asm volatile("cp.async.commit_group;" ::: "memory")
#define CP_WAIT1()  asm volatile("cp.async.wait_group 1;" ::: "memory")

__device__ __forceinline__ void ldsm4(uint32_t& r0, uint32_t& r1, uint32_t& r2,
                                      uint32_t& r3, uint32_t addr) {
    asm volatile("ldmatrix.sync.aligned.m8n8.x4.shared.b16 {%0,%1,%2,%3}, [%4];"
                 : "=r"(r0), "=r"(r1), "=r"(r2), "=r"(r3) : "r"(addr));
}

__device__ __forceinline__ void mma16816(float* c, const uint32_t* a,
                                         uint32_t b0, uint32_t b1) {
    asm volatile(
        "mma.sync.aligned.m16n8k16.row.col.f32.f16.f16.f32 "
        "{%0,%1,%2,%3}, {%4,%5,%6,%7}, {%8,%9}, {%0,%1,%2,%3};"
        : "+f"(c[0]), "+f"(c[1]), "+f"(c[2]), "+f"(c[3])
        : "r"(a[0]), "r"(a[1]), "r"(a[2]), "r"(a[3]), "r"(b0), "r"(b1));
}

__device__ __forceinline__ float gelu_exact(float v) {
    return 0.5f * v * (1.0f + erff(v * 0.70710678118654752f));
}

// transpose+convert one 32x32 tile (256 threads, 32x33 smem scratch)
__device__ __forceinline__ void cvt_tile(const float* __restrict__ s,
                                         __half* __restrict__ d,
                                         float* tsh, int R, int C,
                                         int r0, int c0, int tx, int ty)
{
#pragma unroll
    for (int i = 0; i < 4; i++)
        tsh[(ty + i * 8) * 33 + tx] = s[(size_t)(r0 + ty + i * 8) * C + c0 + tx];
    __syncthreads();
#pragma unroll
    for (int i = 0; i < 4; i++) {
        int orow = c0 + ty + i * 8;
        int ocol = r0 + tx;
        d[(size_t)orow * R + ocol] = __float2half(tsh[tx * 33 + ty + i * 8]);
    }
    __syncthreads();
}

// ---------------- prep: router + both weight conversions, one launch -------
__global__ __launch_bounds__(256) void prep_kernel(
    const float* __restrict__ x, const float* __restrict__ noise,
    const float* __restrict__ rw, const float* __restrict__ rb,
    const float* __restrict__ w1, __half* __restrict__ w1dst,
    const float* __restrict__ w2, __half* __restrict__ w2dst)
{
    __shared__ float sh[32 * 33];
    int bid = blockIdx.x;
    int tid = threadIdx.x;

    if (bid < NB_ROUT) {
        int wid = tid >> 5, lane = tid & 31;
        int t = bid * 8 + wid;
        const float4* xr4 = reinterpret_cast<const float4*>(x + (size_t)t * DIM);
        const float4* rw4 = reinterpret_cast<const float4*>(rw);
        float acc[NEXP];
#pragma unroll
        for (int e = 0; e < NEXP; e++) acc[e] = 0.f;
#pragma unroll
        for (int i = 0; i < 8; i++) {
            int idx = i * 32 + lane;
            float4 xv = xr4[idx];
#pragma unroll
            for (int e = 0; e < NEXP; e++) {
                float4 wv = rw4[e * 256 + idx];
                acc[e] += xv.x * wv.x + xv.y * wv.y + xv.z * wv.z + xv.w * wv.w;
            }
        }
#pragma unroll
        for (int o = 16; o > 0; o >>= 1)
#pragma unroll
            for (int e = 0; e < NEXP; e++)
                acc[e] += __shfl_xor_sync(0xFFFFFFFFu, acc[e], o);
        if (lane == 0) {
            float lg[NEXP];
#pragma unroll
            for (int e = 0; e < NEXP; e++)
                lg[e] = acc[e] + rb[e] + noise[t * NEXP + e] * 0.02f;
            int e1 = 0;
#pragma unroll
            for (int e = 1; e < NEXP; e++) if (lg[e] > lg[e1]) e1 = e;
            int e2 = -1;
#pragma unroll
            for (int e = 0; e < NEXP; e++) {
                if (e == e1) continue;
                if (e2 < 0 || lg[e] > lg[e2]) e2 = e;
            }
            g_selmask[t] = (unsigned char)((1 << e1) | (1 << e2));
        }
        return;
    }

    int tx = tid & 31, ty = tid >> 5;
    if (bid < NB_ROUT + NB_CVT) {
        int cb = bid - NB_ROUT;
#pragma unroll 1
        for (int it = 0; it < 16; it++) {
            int g = cb * 16 + it;
            int e = g >> 12;
            int rem = g & 4095;
            int tr = rem & 31;
            int tc = rem >> 5;
            cvt_tile(w1 + (size_t)e * DIM * DFF, w1dst + (size_t)e * DFF * DIM,
                     sh, DIM, DFF, tr * 32, tc * 32, tx, ty);
        }
        return;
    }
    int cb = bid - NB_ROUT - NB_CVT;
#pragma unroll 1
    for (int it = 0; it < 16; it++) {
        int g = cb * 16 + it;
        int e = g >> 12;
        int rem = g & 4095;
        int tr = rem & 127;
        int tc = rem >> 7;
        cvt_tile(w2 + (size_t)e * DFF * DIM, w2dst + (size_t)e * DIM * DFF,
                 sh, DFF, DIM, tr * 32, tc * 32, tx, ty);
    }
}

// ---------------- route: full routing resolution in one block --------------
__global__ __launch_bounds__(1024) void route_kernel()
{
    __shared__ uint64_t s0[1024], s1[1024];
    __shared__ int sF[NEXP], sOff[NEXP + 1];
    int tid = threadIdx.x;

    union { uint4 q; unsigned char b[16]; } u;
    u.q = reinterpret_cast<const uint4*>(g_selmask)[tid];
    uint32_t m[NEXP];
#pragma unroll
    for (int e = 0; e < NEXP; e++) m[e] = 0;
#pragma unroll
    for (int j = 0; j < 16; j++) {
        unsigned char sm = u.b[j];
#pragma unroll
        for (int e = 0; e < NEXP; e++)
            m[e] |= (uint32_t)((sm >> e) & 1) << j;
    }
    int cnt[NEXP];
#pragma unroll
    for (int e = 0; e < NEXP; e++) cnt[e] = __popc(m[e]);

    uint64_t p0 = (uint64_t)cnt[0] | ((uint64_t)cnt[1] << 16) |
                  ((uint64_t)cnt[2] << 32) | ((uint64_t)cnt[3] << 48);
    uint64_t p1 = (uint64_t)cnt[4] | ((uint64_t)cnt[5] << 16) |
                  ((uint64_t)cnt[6] << 32) | ((uint64_t)cnt[7] << 48);
    s0[tid] = p0; s1[tid] = p1;
    __syncthreads();
    for (int off = 1; off < 1024; off <<= 1) {
        uint64_t a0 = (tid >= off) ? s0[tid - off] : 0;
        uint64_t a1 = (tid >= off) ? s1[tid - off] : 0;
        __syncthreads();
        s0[tid] += a0; s1[tid] += a1;
        __syncthreads();
    }
    uint64_t i0 = s0[tid], i1 = s1[tid];
    int base[NEXP];
#pragma unroll
    for (int e = 0; e < 4; e++)
        base[e] = (int)((i0 >> (16 * e)) & 0xFFFF) - cnt[e];
#pragma unroll
    for (int e = 4; e < NEXP; e++)
        base[e] = (int)((i1 >> (16 * (e - 4))) & 0xFFFF) - cnt[e];

    union { int4 q; signed char c[16]; } fo;
    uint32_t fm[NEXP];
#pragma unroll
    for (int e = 0; e < NEXP; e++) fm[e] = 0;
#pragma unroll
    for (int j = 0; j < 16; j++) {
        int f = -1;
#pragma unroll
        for (int e = NEXP - 1; e >= 0; e--) {
            if ((m[e] >> j) & 1) {
                int rank = base[e] + __popc(m[e] & ((1u << j) - 1u));
                if (rank < CAP) { f = e; break; }
            }
        }
        fo.c[j] = (signed char)f;
        if (f >= 0) fm[f] |= 1u << j;
    }
    reinterpret_cast<int4*>(g_final)[tid] = fo.q;

    int fc[NEXP];
#pragma unroll
    for (int e = 0; e < NEXP; e++) fc[e] = __popc(fm[e]);
    uint64_t q0 = (uint64_t)fc[0] | ((uint64_t)fc[1] << 16) |
                  ((uint64_t)fc[2] << 32) | ((uint64_t)fc[3] << 48);
    uint64_t q1 = (uint64_t)fc[4] | ((uint64_t)fc[5] << 16) |
                  ((uint64_t)fc[6] << 32) | ((uint64_t)fc[7] << 48);
    __syncthreads();
    s0[tid] = q0; s1[tid] = q1;
    __syncthreads();
    for (int off = 1; off < 1024; off <<= 1) {
        uint64_t a0 = (tid >= off) ? s0[tid - off] : 0;
        uint64_t a1 = (tid >= off) ? s1[tid - off] : 0;
        __syncthreads();
        s0[tid] += a0; s1[tid] += a1;
        __syncthreads();
    }
    uint64_t j0 = s0[tid], j1 = s1[tid];
    int fbase[NEXP];
#pragma unroll
    for (int e = 0; e < 4; e++)
        fbase[e] = (int)((j0 >> (16 * e)) & 0xFFFF) - fc[e];
#pragma unroll
    for (int e = 4; e < NEXP; e++)
        fbase[e] = (int)((j1 >> (16 * (e - 4))) & 0xFFFF) - fc[e];

    if (tid == 1023) {
        int o = 0;
        sOff[0] = 0;
        for (int e = 0; e < NEXP; e++) {
            int F = (e < 4) ? (int)((j0 >> (16 * e)) & 0xFFFF)
                            : (int)((j1 >> (16 * (e - 4))) & 0xFFFF);
            sF[e] = F;
            o += ((F + TM - 1) / TM) * TM;
            sOff[e + 1] = o;
        }
    }
    __syncthreads();
    if (tid <= NEXP) g_off[tid] = sOff[tid];

#pragma unroll
    for (int j = 0; j < 16; j++) {
        int f = fo.c[j];
        if (f >= 0) {
            int pos = sOff[f] + fbase[f] + __popc(fm[f] & ((1u << j) - 1u));
            g_perm[pos] = tid * 16 + j;
        }
    }
    for (int e = 0; e < NEXP; e++)
        for (int i = sOff[e] + sF[e] + tid; i < sOff[e + 1]; i += 1024)
            g_perm[i] = TOK;
}

// fat gather: gather + zero-dropped
__global__ __launch_bounds__(256) void gather_kernel(
    const float* __restrict__ x, float* __restrict__ out)
{
    int bid = blockIdx.x;
    int tid = threadIdx.x;
    if (bid < PADMAX) {
        int tok = g_perm[bid];
        float4 v = make_float4(0.f, 0.f, 0.f, 0.f);
        if (tok < TOK)
            v = reinterpret_cast<const float4*>(x + (size_t)tok * DIM)[tid];
        __half h[4];
        h[0] = __float2half(v.x); h[1] = __float2half(v.y);
        h[2] = __float2half(v.z); h[3] = __float2half(v.w);
        reinterpret_cast<uint2*>(g_Ag + (size_t)bid * DIM)[tid] =
            *reinterpret_cast<uint2*>(h);
        return;
    }
    __shared__ int list[256];
    __shared__ int cnt;
    if (tid == 0) cnt = 0;
    __syncthreads();
    int t = (bid - PADMAX) * 256 + tid;
    if (g_final[t] < 0) { int p = atomicAdd(&cnt, 1); list[p] = t; }
    __syncthreads();
    float4 z = make_float4(0.f, 0.f, 0.f, 0.f);
    for (int i = 0; i < cnt; i++) {
        size_t row = (size_t)list[i] * DIM;
        reinterpret_cast<float4*>(out + row)[tid] = z;
    }
}

// ---------------- HMMA GEMM — minimal-issue mainloop -----------------------
// Single barrier per chunk (top sync orders compute(c-1) vs fill(c+1), which
// reuses the stage consumed at c-1). Immediate-offset cp.async; persistent
// fill pointers (+KC/chunk); stage pointers rotated without %3.
template<int KT, int NT, int MODE>
__global__ __launch_bounds__(256, 2) void gemm_kernel(
    const __half* __restrict__ A, const __half* __restrict__ B,
    const float* __restrict__ bias, float* __restrict__ out)
{
    int row0 = blockIdx.y * TM;
    if (row0 >= g_off[NEXP]) return;
    int e = 0;
#pragma unroll
    for (int i = 0; i < NEXP; i++) if (row0 >= g_off[i + 1]) e = i + 1;
    int n0 = blockIdx.x * 128;

    extern __shared__ __align__(1024) char smem_raw[];
    uint32_t sb = (smem_u32(smem_raw) + 1023) & ~1023u;

    int tid = threadIdx.x;
    int lane = tid & 31;
    int wid = tid >> 5;
    int wm = wid & 3;
    int wn = wid >> 2;
    int lrow = (lane & 7) + ((lane >> 3) & 1) * 8;
    int lkh2 = ((lane >> 4) * 8) * 2;

    constexpr int C = KT >> 6;

    // fill addressing: this thread writes rows (tid>>3)+32j at kp=(tid&7)
    uint32_t so = SWZ128(((tid >> 3) << 7) + ((tid & 7) << 4));
    const char* fA = (const char*)(A + (size_t)(row0 + (tid >> 3)) * KT
                                     + (tid & 7) * 8);
    const char* fB = (const char*)(B + ((size_t)e * NT + n0 + (tid >> 3)) * KT
                                     + (tid & 7) * 8);

    auto fill_stage = [&](uint32_t st, const char* a, const char* b) {
        uint32_t dA = st + so, dB = st + 16384 + so;
        CP16I(dA, a,     0, 0);
        CP16I(dA, a,  4096, 64 * KT);
        CP16I(dA, a,  8192, 128 * KT);
        CP16I(dA, a, 12288, 192 * KT);
        CP16I(dB, b,     0, 0);
        CP16I(dB, b,  4096, 64 * KT);
        CP16I(dB, b,  8192, 128 * KT);
        CP16I(dB, b, 12288, 192 * KT);
    };

    uint32_t arel[2], brel[4];
#pragma unroll
    for (int mt = 0; mt < 2; mt++)
        arel[mt] = SWZ128(((wm * 32 + mt * 16 + lrow) << 7) + lkh2);
#pragma unroll
    for (int nt = 0; nt < 4; nt++)
        brel[nt] = 16384u + SWZ128(((wn * 64 + nt * 16 + lrow) << 7) + lkh2);

    float acc[2][8][4];
#pragma unroll
    for (int mt = 0; mt < 2; mt++)
#pragma unroll
        for (int nf = 0; nf < 8; nf++)
#pragma unroll
            for (int q = 0; q < 4; q++) acc[mt][nf][q] = 0.f;

    fill_stage(sb,         fA,            fB);            CP_COMMIT();
    fill_stage(sb + STAGE, fA + 2 * KC,   fB + 2 * KC);   CP_COMMIT();
    const char* pA = fA + 4 * KC;       // bytes: chunk 2 (KC elems = 2*KC B)
    const char* pB = fB + 4 * KC;

    uint32_t stC = sb;                  // compute stage
    uint32_t stF = sb + 2 * STAGE;      // fill stage
    const uint32_t stEnd = sb + 3 * STAGE;

#pragma unroll 1
    for (int c = 0; c < C; ++c) {
        CP_WAIT1();
        __syncthreads();
        if (c + 2 < C) {
            fill_stage(stF, pA, pB);
            pA += 2 * KC; pB += 2 * KC;
        }
        CP_COMMIT();
        uint32_t ab0 = stC + arel[0], ab1 = stC + arel[1];
        uint32_t bb0 = stC + brel[0], bb1 = stC + brel[1];
        uint32_t bb2 = stC + brel[2], bb3 = stC + brel[3];
#pragma unroll
        for (int ks = 0; ks < 4; ks++) {
            uint32_t kx = (uint32_t)ks << 5;
            uint32_t a[2][4], bh[4][4];
            ldsm4(a[0][0], a[0][1], a[0][2], a[0][3], ab0 ^ kx);
            ldsm4(a[1][0], a[1][1], a[1][2], a[1][3], ab1 ^ kx);
            ldsm4(bh[0][0], bh[0][1], bh[0][2], bh[0][3], bb0 ^ kx);
            ldsm4(bh[1][0], bh[1][1], bh[1][2], bh[1][3], bb1 ^ kx);
            ldsm4(bh[2][0], bh[2][1], bh[2][2], bh[2][3], bb2 ^ kx);
            ldsm4(bh[3][0], bh[3][1], bh[3][2], bh[3][3], bb3 ^ kx);
#pragma unroll
            for (int mt = 0; mt < 2; mt++)
#pragma unroll
                for (int nt = 0; nt < 4; nt++) {
                    mma16816(acc[mt][nt * 2],     a[mt], bh[nt][0], bh[nt][2]);
                    mma16816(acc[mt][nt * 2 + 1], a[mt], bh[nt][1], bh[nt][3]);
                }
        }
        stC += STAGE; if (stC == stEnd) stC = sb;
        stF += STAGE; if (stF == stEnd) stF = sb;
    }

    // ---- epilogue ----
    int colb = (lane & 3) * 2;
#pragma unroll
    for (int mt = 0; mt < 2; mt++) {
        int rA = row0 + wm * 32 + mt * 16 + (lane >> 2);
        int rB = rA + 8;
        int tokA = 0, tokB = 0;
        if (MODE == 2) { tokA = g_perm[rA]; tokB = g_perm[rB]; }
#pragma unroll
        for (int nf = 0; nf < 8; nf++) {
            int col = n0 + wn * 64 + nf * 8 + colb;
            float bi0 = bias[(size_t)e * NT + col];
            float bi1 = bias[(size_t)e * NT + col + 1];
            float vA0 = acc[mt][nf][0] + bi0, vA1 = acc[mt][nf][1] + bi1;
            float vB0 = acc[mt][nf][2] + bi0, vB1 = acc[mt][nf][3] + bi1;
            if (MODE == 1) {
                __half2 hA, hB;
                hA.x = __float2half(gelu_exact(vA0));
                hA.y = __float2half(gelu_exact(vA1));
                hB.x = __float2half(gelu_exact(vB0));
                hB.y = __float2half(gelu_exact(vB1));
                *reinterpret_cast<__half2*>(g_H + (size_t)rA * DFF + col) = hA;
                *reinterpret_cast<__half2*>(g_H + (size_t)rB * DFF + col) = hB;
            } else {
                if (tokA < TOK)
                    *reinterpret_cast<float2*>(out + (size_t)tokA * DIM + col) =
                        make_float2(vA0, vA1);
                if (tokB < TOK)
                    *reinterpret_cast<float2*>(out + (size_t)tokB * DIM + col) =
                        make_float2(vB0, vB1);
            }
        }
    }
}

// ---------------- launch (single stream; no events — graph-capture safe) ----
extern "C" void kernel_launch(void* const* d_in, const int* in_sizes, int n_in,
                              void* d_out, int out_size)
{
    const float* x     = (const float*)d_in[0];
    const float* noise = (const float*)d_in[1];
    const float* rw    = (const float*)d_in[2];
    const float* rb    = (const float*)d_in[3];
    const float* w1    = (const float*)d_in[4];
    const float* b1    = (const float*)d_in[5];
    const float* w2    = (const float*)d_in[6];
    const float* b2    = (const float*)d_in[7];
    float* out = (float*)d_out;

    static __half *p_W1, *p_W2, *p_Ag, *p_H;
    static bool resolved = false;
    if (!resolved) {
        cudaGetSymbolAddress((void**)&p_W1, g_W1);
        cudaGetSymbolAddress((void**)&p_W2, g_W2);
        cudaGetSymbolAddress((void**)&p_Ag, g_Ag);
        cudaGetSymbolAddress((void**)&p_H, g_H);
        cudaFuncSetAttribute(gemm_kernel<DIM, DFF, 1>,
                             cudaFuncAttributeMaxDynamicSharedMemorySize, SMEM_REQ);
        cudaFuncSetAttribute(gemm_kernel<DFF, DIM, 2>,
                             cudaFuncAttributeMaxDynamicSharedMemorySize, SMEM_REQ);
        resolved = true;
    }

    // 1: router + W1 convert + W2 convert (one fat, small-smem launch)
    prep_kernel<<<NB_ROUT + 2 * NB_CVT, 256>>>(x, noise, rw, rb,
                                               w1, p_W1, w2, p_W2);
    // 2: full routing resolution in one block
    route_kernel<<<1, 1024>>>();
    // 3: gather + zero-dropped
    gather_kernel<<<PADMAX + TOK / 256, 256>>>(x, out);

    // 4: FFN pass 1: H = gelu(Xg @ W1^T + b1)   K=1024, N=4096
    gemm_kernel<DIM, DFF, 1><<<dim3(DFF / 128, MAXROWTILES), 256, SMEM_REQ>>>(
        p_Ag, p_W1, b1, nullptr);

    // 5: FFN pass 2: out = H @ W2^T + b2 (scatter)   K=4096, N=1024
    gemm_kernel<DFF, DIM, 2><<<dim3(DIM / 128, MAXROWTILES), 256, SMEM_REQ>>>(
        p_H, p_W2, b2, out);
}